// round 1
// baseline (speedup 1.0000x reference)
#include <cuda_runtime.h>
#include <cuda_bf16.h>
#include <math.h>

// Problem sizes (fixed by reference)
#define BATCH 64
#define SEQ   1024
#define EDIM  256
#define HDIM  256
#define MTOT  (BATCH * SEQ)   // 65536

// Scratch for q, k, v projections (static device arrays: allowed)
__device__ float g_q[(size_t)MTOT * HDIM];
__device__ float g_k[(size_t)MTOT * HDIM];
__device__ float g_v[(size_t)MTOT * EDIM];

// ---------------------------------------------------------------------------
// Kernel 1: QKV projection.  C[M, 256] = X[M, 256] @ W[256, 256] + b
// grid = (HDIM/64, MTOT/64, 3), block = 256 threads, 64x64 tile, 4x4/thread.
// ---------------------------------------------------------------------------
__global__ __launch_bounds__(256, 4)
void qkv_kernel(const float* __restrict__ X,
                const float* __restrict__ Wq, const float* __restrict__ bq,
                const float* __restrict__ Wk, const float* __restrict__ bk,
                const float* __restrict__ Wv, const float* __restrict__ bv)
{
    const float* W;
    const float* bias;
    float* out;
    if (blockIdx.z == 0)      { W = Wq; bias = bq; out = g_q; }
    else if (blockIdx.z == 1) { W = Wk; bias = bk; out = g_k; }
    else                      { W = Wv; bias = bv; out = g_v; }

    const int BK = 16;
    __shared__ __align__(16) float As[BK][64 + 4];
    __shared__ __align__(16) float Bs[BK][64 + 4];

    const int m0 = blockIdx.y * 64;
    const int n0 = blockIdx.x * 64;
    const int t  = threadIdx.x;        // 0..255
    const int tx = t % 16;             // output col group
    const int ty = t / 16;             // output row group

    float acc[4][4];
#pragma unroll
    for (int i = 0; i < 4; i++)
#pragma unroll
        for (int j = 0; j < 4; j++) acc[i][j] = 0.f;

    for (int k0 = 0; k0 < EDIM; k0 += BK) {
        // Load X tile [64 x 16] (transposed into As)
        {
            int r  = t / 4;            // 0..63
            int c4 = (t % 4) * 4;      // 0,4,8,12
            float4 v = *(const float4*)(X + (size_t)(m0 + r) * EDIM + k0 + c4);
            As[c4 + 0][r] = v.x;
            As[c4 + 1][r] = v.y;
            As[c4 + 2][r] = v.z;
            As[c4 + 3][r] = v.w;
        }
        // Load W tile [16 x 64]
        {
            int r  = t / 16;           // 0..15
            int c4 = (t % 16) * 4;     // 0..60
            float4 v = *(const float4*)(W + (size_t)(k0 + r) * HDIM + n0 + c4);
            *(float4*)&Bs[r][c4] = v;
        }
        __syncthreads();

#pragma unroll
        for (int k = 0; k < BK; k++) {
            float a[4], b[4];
            *(float4*)a = *(const float4*)&As[k][ty * 4];
            *(float4*)b = *(const float4*)&Bs[k][tx * 4];
#pragma unroll
            for (int i = 0; i < 4; i++)
#pragma unroll
                for (int j = 0; j < 4; j++) acc[i][j] = fmaf(a[i], b[j], acc[i][j]);
        }
        __syncthreads();
    }

    const int row = m0 + ty * 4;
    const int col = n0 + tx * 4;
    float4 bb = *(const float4*)(bias + col);
#pragma unroll
    for (int i = 0; i < 4; i++) {
        float4 o;
        o.x = acc[i][0] + bb.x;
        o.y = acc[i][1] + bb.y;
        o.z = acc[i][2] + bb.z;
        o.w = acc[i][3] + bb.w;
        *(float4*)(out + (size_t)(row + i) * HDIM + col) = o;
    }
}

// ---------------------------------------------------------------------------
// Kernel 2: fused flash-style attention.
// grid = (SEQ/64, BATCH), block = 256 threads.
// CTA handles 64 queries of one batch; streams K/V in 64-key tiles.
// Thread (tq = t/16, tk = t%16):
//   QK phase: queries {tq+16i}, keys {tk+16j}          -> s[4][4]
//   PV phase: queries {tq+16i}, dims {td*4+64c}, td=tk -> acc[4][4][4]
// ---------------------------------------------------------------------------
#define LDK 260                     // 256 + 4 pad (row stride, floats)
#define LDP 68                      // P tile row stride

__global__ __launch_bounds__(256, 1)
void attn_kernel(float* __restrict__ out)
{
    extern __shared__ __align__(16) float sm[];
    float* Qs   = sm;                       // 64 * 260
    float* Ks   = Qs + 64 * LDK;            // 64 * 260
    float* Vs   = Ks + 64 * LDK;            // 64 * 260
    float* Ps   = Vs + 64 * LDK;            // 64 * 68
    float* mrow = Ps + 64 * LDP;            // 64
    float* lrow = mrow + 64;                // 64
    float* crow = lrow + 64;                // 64

    const int b  = blockIdx.y;
    const int qt = blockIdx.x;              // query tile 0..15
    const int t  = threadIdx.x;

    const float* qg = g_q + ((size_t)b * SEQ + qt * 64) * HDIM;
    const float* kg = g_k + (size_t)b * SEQ * HDIM;
    const float* vg = g_v + (size_t)b * SEQ * EDIM;

    // Load Q tile [64 x 256]
    for (int i = t; i < 64 * 64; i += 256) {
        int r = i / 64, c = i % 64;
        *(float4*)&Qs[r * LDK + c * 4] = *(const float4*)(qg + (size_t)r * HDIM + c * 4);
    }
    if (t < 64) { mrow[t] = -1e30f; lrow[t] = 0.f; }

    const int tq = t / 16;
    const int tk = t % 16;   // also td in PV phase

    float acc[4][4][4];
#pragma unroll
    for (int i = 0; i < 4; i++)
#pragma unroll
        for (int c = 0; c < 4; c++)
#pragma unroll
            for (int e = 0; e < 4; e++) acc[i][c][e] = 0.f;

    __syncthreads();

    for (int kt = 0; kt < SEQ / 64; kt++) {
        // Load K, V tiles [64 x 256]
        const float* kp = kg + (size_t)kt * 64 * HDIM;
        const float* vp = vg + (size_t)kt * 64 * EDIM;
        for (int i = t; i < 64 * 64; i += 256) {
            int r = i / 64, c = i % 64;
            *(float4*)&Ks[r * LDK + c * 4] = *(const float4*)(kp + (size_t)r * HDIM + c * 4);
            *(float4*)&Vs[r * LDK + c * 4] = *(const float4*)(vp + (size_t)r * EDIM + c * 4);
        }
        __syncthreads();

        // ---- S = Q @ K^T (64x64 tile), unscaled ----
        float s[4][4];
#pragma unroll
        for (int i = 0; i < 4; i++)
#pragma unroll
            for (int j = 0; j < 4; j++) s[i][j] = 0.f;

        for (int d = 0; d < HDIM; d += 4) {
            float4 qv[4], kv[4];
#pragma unroll
            for (int i = 0; i < 4; i++) qv[i] = *(const float4*)&Qs[(tq + 16 * i) * LDK + d];
#pragma unroll
            for (int j = 0; j < 4; j++) kv[j] = *(const float4*)&Ks[(tk + 16 * j) * LDK + d];
#pragma unroll
            for (int i = 0; i < 4; i++)
#pragma unroll
                for (int j = 0; j < 4; j++) {
                    s[i][j] = fmaf(qv[i].x, kv[j].x, s[i][j]);
                    s[i][j] = fmaf(qv[i].y, kv[j].y, s[i][j]);
                    s[i][j] = fmaf(qv[i].z, kv[j].z, s[i][j]);
                    s[i][j] = fmaf(qv[i].w, kv[j].w, s[i][j]);
                }
        }
#pragma unroll
        for (int i = 0; i < 4; i++)
#pragma unroll
            for (int j = 0; j < 4; j++)
                Ps[(tq + 16 * i) * LDP + (tk + 16 * j)] = s[i][j];
        __syncthreads();

        // ---- Online softmax row update (threads 0..63, one row each) ----
        if (t < 64) {
            float m_old = mrow[t];
            float mx = m_old;
            float* pr = &Ps[t * LDP];
#pragma unroll 8
            for (int j = 0; j < 64; j++) mx = fmaxf(mx, pr[j]);
            float corr = expf(m_old - mx);
            float sum = 0.f;
#pragma unroll 8
            for (int j = 0; j < 64; j++) {
                float p = expf(pr[j] - mx);
                pr[j] = p;
                sum += p;
            }
            mrow[t] = mx;
            lrow[t] = lrow[t] * corr + sum;
            crow[t] = corr;
        }
        __syncthreads();

        // ---- Rescale accumulators, then O += P @ V ----
        float cq[4];
#pragma unroll
        for (int i = 0; i < 4; i++) cq[i] = crow[tq + 16 * i];
#pragma unroll
        for (int i = 0; i < 4; i++)
#pragma unroll
            for (int c = 0; c < 4; c++)
#pragma unroll
                for (int e = 0; e < 4; e++) acc[i][c][e] *= cq[i];

        for (int kk = 0; kk < 64; kk++) {
            float p[4];
#pragma unroll
            for (int i = 0; i < 4; i++) p[i] = Ps[(tq + 16 * i) * LDP + kk];
            float4 vv[4];
#pragma unroll
            for (int c = 0; c < 4; c++) vv[c] = *(const float4*)&Vs[kk * LDK + c * 64 + tk * 4];
#pragma unroll
            for (int i = 0; i < 4; i++)
#pragma unroll
                for (int c = 0; c < 4; c++) {
                    acc[i][c][0] = fmaf(p[i], vv[c].x, acc[i][c][0]);
                    acc[i][c][1] = fmaf(p[i], vv[c].y, acc[i][c][1]);
                    acc[i][c][2] = fmaf(p[i], vv[c].z, acc[i][c][2]);
                    acc[i][c][3] = fmaf(p[i], vv[c].w, acc[i][c][3]);
                }
        }
        __syncthreads();   // protect K/V/P before next tile
    }

    // ---- Epilogue: divide by l, write out ----
#pragma unroll
    for (int i = 0; i < 4; i++) {
        int qrow = tq + 16 * i;
        float inv = 1.f / lrow[qrow];
        size_t base = ((size_t)b * SEQ + qt * 64 + qrow) * EDIM;
#pragma unroll
        for (int c = 0; c < 4; c++) {
            float4 o;
            o.x = acc[i][c][0] * inv;
            o.y = acc[i][c][1] * inv;
            o.z = acc[i][c][2] * inv;
            o.w = acc[i][c][3] * inv;
            *(float4*)(out + base + c * 64 + tk * 4) = o;
        }
    }
}

// ---------------------------------------------------------------------------
extern "C" void kernel_launch(void* const* d_in, const int* in_sizes, int n_in,
                              void* d_out, int out_size)
{
    const float* x  = (const float*)d_in[0];
    const float* Wq = (const float*)d_in[1];
    const float* bq = (const float*)d_in[2];
    const float* Wk = (const float*)d_in[3];
    const float* bk = (const float*)d_in[4];
    const float* Wv = (const float*)d_in[5];
    const float* bv = (const float*)d_in[6];
    float* out = (float*)d_out;

    // QKV projections
    dim3 g1(HDIM / 64, MTOT / 64, 3);
    qkv_kernel<<<g1, 256>>>(x, Wq, bq, Wk, bk, Wv, bv);

    // Fused attention
    const int smem_bytes = (3 * 64 * LDK + 64 * LDP + 3 * 64) * (int)sizeof(float);
    cudaFuncSetAttribute(attn_kernel, cudaFuncAttributeMaxDynamicSharedMemorySize, smem_bytes);
    dim3 g2(SEQ / 64, BATCH);
    attn_kernel<<<g2, 256, smem_bytes>>>(out);
}

// round 3
// speedup vs baseline: 3.1301x; 3.1301x over previous
#include <cuda_runtime.h>
#include <cuda_bf16.h>
#include <cstdint>
#include <math.h>

// ---------------------------------------------------------------------------
#define BATCH 64
#define SEQ   1024
#define EDIM  256
#define HDIM  256
#define MTOT  (BATCH * SEQ)       // 65536

// Scratch (__device__ globals: sanctioned no-alloc workaround)
__device__ float g_q  [(size_t)MTOT * HDIM];          // 64 MB
__device__ float g_k  [(size_t)MTOT * HDIM];          // 64 MB
__device__ float g_vt [(size_t)BATCH * EDIM * SEQ];   // 64 MB   V^T per batch [d][s]
__device__ float g_s  [(size_t)BATCH * SEQ * SEQ];    // 256 MB  scores -> P in place
__device__ float g_wqT[EDIM * HDIM];
__device__ float g_wkT[EDIM * HDIM];
__device__ float g_wvT[EDIM * HDIM];

// ---------------------------------------------------------------------------
// helpers
// ---------------------------------------------------------------------------
__device__ __forceinline__ uint32_t smem_u32(const void* p) {
    uint32_t a;
    asm("{ .reg .u64 t; cvta.to.shared.u64 t, %1; cvt.u32.u64 %0, t; }" : "=r"(a) : "l"(p));
    return a;
}

__device__ __forceinline__ void ldsm_x4(uint32_t* r, uint32_t addr) {
    asm volatile("ldmatrix.sync.aligned.m8n8.x4.shared.b16 {%0,%1,%2,%3}, [%4];"
                 : "=r"(r[0]), "=r"(r[1]), "=r"(r[2]), "=r"(r[3]) : "r"(addr));
}
__device__ __forceinline__ void ldsm_x2(uint32_t* r, uint32_t addr) {
    asm volatile("ldmatrix.sync.aligned.m8n8.x2.shared.b16 {%0,%1}, [%2];"
                 : "=r"(r[0]), "=r"(r[1]) : "r"(addr));
}

__device__ __forceinline__ void mma_bf16(float* c, const uint32_t* a, const uint32_t* b) {
    asm volatile(
        "mma.sync.aligned.m16n8k16.row.col.f32.bf16.bf16.f32 "
        "{%0,%1,%2,%3}, {%4,%5,%6,%7}, {%8,%9}, {%0,%1,%2,%3};"
        : "+f"(c[0]), "+f"(c[1]), "+f"(c[2]), "+f"(c[3])
        : "r"(a[0]), "r"(a[1]), "r"(a[2]), "r"(a[3]), "r"(b[0]), "r"(b[1]));
}

// hi/lo bf16 split of two floats, packed as bf16x2 words
__device__ __forceinline__ void split2(float x, float y, uint32_t& h, uint32_t& l) {
    __nv_bfloat162 H = __floats2bfloat162_rn(x, y);
    float hx = __bfloat162float(__low2bfloat16(H));
    float hy = __bfloat162float(__high2bfloat16(H));
    __nv_bfloat162 L = __floats2bfloat162_rn(x - hx, y - hy);
    h = *reinterpret_cast<uint32_t*>(&H);
    l = *reinterpret_cast<uint32_t*>(&L);
}

// ---------------------------------------------------------------------------
// GEMM: C[128 x 128] = A[128 x K] @ B[128 x K]^T  via bf16x3 mma.sync
// Both A and B stored K-major in gmem. K consumed in chunks of 32 floats.
// smem: per stage {Ahi, Alo, Bhi, Blo}, each 128 rows x 32 bf16 (+pad to 40)
// ---------------------------------------------------------------------------
#define ROWB   80                  // bytes per smem row (40 bf16)
#define REG_SZ (128 * ROWB)        // 10240
#define OFF_AHI 0
#define OFF_ALO (REG_SZ)
#define OFF_BHI (2 * REG_SZ)
#define OFF_BLO (3 * REG_SZ)
#define STAGE_SZ (4 * REG_SZ)      // 40960
#define SMEM_SZ  (2 * STAGE_SZ)    // 81920

enum { M_PROJQK = 0, M_PROJVT = 1, M_QK = 2, M_PV = 3 };

template<int MODE, int NCHUNK>
__global__ __launch_bounds__(256, 1)
void gemm_bf16x3(const float* __restrict__ x,
                 const float* __restrict__ bq, const float* __restrict__ bk,
                 const float* __restrict__ bv, float* __restrict__ out)
{
    extern __shared__ __align__(128) char smem[];
    const uint32_t sbase = smem_u32(smem);
    const int t    = threadIdx.x;
    const int lane = t & 31;
    const int wid  = t >> 5;
    const int wm   = wid >> 2;        // 0..1  (64-row warp slab)
    const int wn   = wid & 3;         // 0..3  (32-col warp slab)

    // ---- operand resolution ----
    const float* Aptr; const float* Bptr; const float* bias = nullptr;
    float* Cptr; size_t lda, ldb, ldc;
    // bias_mode: 0 none, 1 column bias (bias[n]), 2 row bias (bias[m])
    int bias_mode = 0;

    if (MODE == M_PROJQK) {
        int mt = blockIdx.x, nt = blockIdx.y, qk = blockIdx.z;
        Aptr = x + (size_t)mt * 128 * EDIM;                 lda = EDIM;
        Bptr = (qk ? g_wkT : g_wqT) + (size_t)nt * 128 * EDIM; ldb = EDIM;
        Cptr = (qk ? g_k : g_q) + (size_t)mt * 128 * HDIM + nt * 128; ldc = HDIM;
        bias = (qk ? bk : bq) + nt * 128;                   bias_mode = 1;
    } else if (MODE == M_PROJVT) {
        int dt = blockIdx.x, st = blockIdx.y, b = blockIdx.z;
        Aptr = g_wvT + (size_t)dt * 128 * EDIM;             lda = EDIM;
        Bptr = x + ((size_t)b * SEQ + st * 128) * EDIM;     ldb = EDIM;
        Cptr = g_vt + (size_t)b * EDIM * SEQ + (size_t)dt * 128 * SEQ + st * 128; ldc = SEQ;
        bias = bv + dt * 128;                               bias_mode = 2;
    } else if (MODE == M_QK) {
        int mt = blockIdx.x, nt = blockIdx.y, b = blockIdx.z;
        Aptr = g_q + ((size_t)b * SEQ + mt * 128) * HDIM;   lda = HDIM;
        Bptr = g_k + ((size_t)b * SEQ + nt * 128) * HDIM;   ldb = HDIM;
        Cptr = g_s + (size_t)b * SEQ * SEQ + (size_t)mt * 128 * SEQ + nt * 128; ldc = SEQ;
    } else { // M_PV
        int mt = blockIdx.x, nt = blockIdx.y, b = blockIdx.z;
        Aptr = g_s + (size_t)b * SEQ * SEQ + (size_t)mt * 128 * SEQ; lda = SEQ;
        Bptr = g_vt + (size_t)b * EDIM * SEQ + (size_t)nt * 128 * SEQ; ldb = SEQ;
        Cptr = out + ((size_t)b * SEQ + mt * 128) * EDIM + nt * 128; ldc = EDIM;
    }

    float acc[4][4][4];
#pragma unroll
    for (int i = 0; i < 4; i++)
#pragma unroll
        for (int j = 0; j < 4; j++)
#pragma unroll
            for (int e = 0; e < 4; e++) acc[i][j][e] = 0.f;

    // per-thread gmem load slots (chunk = 128 rows x 32 floats, 4 float4 each side)
    float4 va[4], vb[4];
    const int r_ld  = t >> 3;            // 0..31 base row step 32
    const int c4_ld = (t & 7) << 2;      // float col 0,4,..,28

#define LOAD_CHUNK(J)                                                          \
    {                                                                          \
        const float* Ak = Aptr + (J) * 32;                                     \
        const float* Bk = Bptr + (J) * 32;                                     \
        _Pragma("unroll")                                                      \
        for (int i = 0; i < 4; i++) {                                          \
            int r = r_ld + 32 * i;                                             \
            va[i] = *(const float4*)(Ak + (size_t)r * lda + c4_ld);            \
            vb[i] = *(const float4*)(Bk + (size_t)r * ldb + c4_ld);            \
        }                                                                      \
    }

#define STORE_CHUNK(BUF)                                                       \
    {                                                                          \
        char* sp = smem + (BUF) * STAGE_SZ;                                    \
        _Pragma("unroll")                                                      \
        for (int i = 0; i < 4; i++) {                                          \
            int r = r_ld + 32 * i;                                             \
            uint32_t off = (uint32_t)(r * ROWB + c4_ld * 2);                   \
            uint32_t h01, h23, l01, l23;                                       \
            split2(va[i].x, va[i].y, h01, l01);                                \
            split2(va[i].z, va[i].w, h23, l23);                                \
            *(uint2*)(sp + OFF_AHI + off) = make_uint2(h01, h23);              \
            *(uint2*)(sp + OFF_ALO + off) = make_uint2(l01, l23);              \
            split2(vb[i].x, vb[i].y, h01, l01);                                \
            split2(vb[i].z, vb[i].w, h23, l23);                                \
            *(uint2*)(sp + OFF_BHI + off) = make_uint2(h01, h23);              \
            *(uint2*)(sp + OFF_BLO + off) = make_uint2(l01, l23);              \
        }                                                                      \
    }

    LOAD_CHUNK(0);
    STORE_CHUNK(0);
    __syncthreads();

    // fragment smem byte offsets (within a region)
    const uint32_t aoff = (uint32_t)((wm * 64 + (lane & 15)) * ROWB + ((lane >> 4) << 4));
    const uint32_t boff = (uint32_t)((wn * 32 + (lane & 7)) * ROWB + (((lane >> 3) & 1) << 4));

#pragma unroll 1
    for (int j = 0; j < NCHUNK; j++) {
        if (j + 1 < NCHUNK) LOAD_CHUNK(j + 1);

        const uint32_t st = sbase + (uint32_t)((j & 1) * STAGE_SZ);
#pragma unroll
        for (int ks = 0; ks < 2; ks++) {
            const uint32_t kb = (uint32_t)(ks * 32);
            uint32_t ah[4][4], al[4][4], bh[4][2], bl[4][2];
#pragma unroll
            for (int mf = 0; mf < 4; mf++) {
                uint32_t a = aoff + (uint32_t)(mf * 16 * ROWB) + kb;
                ldsm_x4(ah[mf], st + OFF_AHI + a);
                ldsm_x4(al[mf], st + OFF_ALO + a);
            }
#pragma unroll
            for (int nf = 0; nf < 4; nf++) {
                uint32_t b = boff + (uint32_t)(nf * 8 * ROWB) + kb;
                ldsm_x2(bh[nf], st + OFF_BHI + b);
                ldsm_x2(bl[nf], st + OFF_BLO + b);
            }
#pragma unroll
            for (int mf = 0; mf < 4; mf++)
#pragma unroll
                for (int nf = 0; nf < 4; nf++) mma_bf16(acc[mf][nf], ah[mf], bh[nf]);
#pragma unroll
            for (int mf = 0; mf < 4; mf++)
#pragma unroll
                for (int nf = 0; nf < 4; nf++) mma_bf16(acc[mf][nf], ah[mf], bl[nf]);
#pragma unroll
            for (int mf = 0; mf < 4; mf++)
#pragma unroll
                for (int nf = 0; nf < 4; nf++) mma_bf16(acc[mf][nf], al[mf], bh[nf]);
        }

        if (j + 1 < NCHUNK) STORE_CHUNK((j + 1) & 1);
        __syncthreads();
    }

    // ---- epilogue: registers -> gmem ----
#pragma unroll
    for (int mf = 0; mf < 4; mf++) {
        const int r0 = wm * 64 + mf * 16 + (lane >> 2);
        const int r1 = r0 + 8;
        float rb0 = 0.f, rb1 = 0.f;
        if (bias_mode == 2) { rb0 = bias[r0]; rb1 = bias[r1]; }
#pragma unroll
        for (int nf = 0; nf < 4; nf++) {
            const int c = wn * 32 + nf * 8 + ((lane & 3) << 1);
            float cb0 = 0.f, cb1 = 0.f;
            if (bias_mode == 1) { cb0 = bias[c]; cb1 = bias[c + 1]; }
            float2 v0, v1;
            v0.x = acc[mf][nf][0] + cb0 + rb0;
            v0.y = acc[mf][nf][1] + cb1 + rb0;
            v1.x = acc[mf][nf][2] + cb0 + rb1;
            v1.y = acc[mf][nf][3] + cb1 + rb1;
            *(float2*)(Cptr + (size_t)r0 * ldc + c) = v0;
            *(float2*)(Cptr + (size_t)r1 * ldc + c) = v1;
        }
    }
}

// ---------------------------------------------------------------------------
// Weight transpose: dst[n][k] = W[k][n]
// ---------------------------------------------------------------------------
__global__ __launch_bounds__(256) void transpose_w(const float* __restrict__ Wq,
                                                   const float* __restrict__ Wk,
                                                   const float* __restrict__ Wv)
{
    const float* src = (blockIdx.x == 0) ? Wq : (blockIdx.x == 1) ? Wk : Wv;
    float* dst = (blockIdx.x == 0) ? g_wqT : (blockIdx.x == 1) ? g_wkT : g_wvT;
    __shared__ float sm[32 * 33];
    int w = threadIdx.x >> 5, l = threadIdx.x & 31;
    for (int ti = 0; ti < 8; ti++)
        for (int tj = 0; tj < 8; tj++) {
#pragma unroll
            for (int k = 0; k < 4; k++) {
                int r = w * 4 + k;
                sm[r * 33 + l] = src[(size_t)(ti * 32 + r) * 256 + tj * 32 + l];
            }
            __syncthreads();
#pragma unroll
            for (int k = 0; k < 4; k++) {
                int r = w * 4 + k;
                dst[(size_t)(tj * 32 + r) * 256 + ti * 32 + l] = sm[l * 33 + r];
            }
            __syncthreads();
        }
}

// ---------------------------------------------------------------------------
// Softmax: one warp per row of g_s (1024 floats), normalized in place
// ---------------------------------------------------------------------------
__global__ __launch_bounds__(256) void softmax_rows()
{
    const int row = blockIdx.x * 8 + (threadIdx.x >> 5);
    const int l   = threadIdx.x & 31;
    float4* p = (float4*)(g_s + (size_t)row * SEQ);

    float4 v[8];
    float mx = -3.4e38f;
#pragma unroll
    for (int i = 0; i < 8; i++) {
        v[i] = p[i * 32 + l];
        mx = fmaxf(mx, fmaxf(fmaxf(v[i].x, v[i].y), fmaxf(v[i].z, v[i].w)));
    }
#pragma unroll
    for (int o = 16; o > 0; o >>= 1) mx = fmaxf(mx, __shfl_xor_sync(0xffffffffu, mx, o));

    float sum = 0.f;
#pragma unroll
    for (int i = 0; i < 8; i++) {
        v[i].x = __expf(v[i].x - mx); v[i].y = __expf(v[i].y - mx);
        v[i].z = __expf(v[i].z - mx); v[i].w = __expf(v[i].w - mx);
        sum += (v[i].x + v[i].y) + (v[i].z + v[i].w);
    }
#pragma unroll
    for (int o = 16; o > 0; o >>= 1) sum += __shfl_xor_sync(0xffffffffu, sum, o);

    const float inv = 1.f / sum;
#pragma unroll
    for (int i = 0; i < 8; i++) {
        v[i].x *= inv; v[i].y *= inv; v[i].z *= inv; v[i].w *= inv;
        p[i * 32 + l] = v[i];
    }
}

// ---------------------------------------------------------------------------
extern "C" void kernel_launch(void* const* d_in, const int* in_sizes, int n_in,
                              void* d_out, int out_size)
{
    const float* x  = (const float*)d_in[0];
    const float* Wq = (const float*)d_in[1];
    const float* bq = (const float*)d_in[2];
    const float* Wk = (const float*)d_in[3];
    const float* bk = (const float*)d_in[4];
    const float* Wv = (const float*)d_in[5];
    const float* bv = (const float*)d_in[6];
    float* out = (float*)d_out;

    cudaFuncSetAttribute(gemm_bf16x3<M_PROJQK, 8>, cudaFuncAttributeMaxDynamicSharedMemorySize, SMEM_SZ);
    cudaFuncSetAttribute(gemm_bf16x3<M_PROJVT, 8>, cudaFuncAttributeMaxDynamicSharedMemorySize, SMEM_SZ);
    cudaFuncSetAttribute(gemm_bf16x3<M_QK, 8>,     cudaFuncAttributeMaxDynamicSharedMemorySize, SMEM_SZ);
    cudaFuncSetAttribute(gemm_bf16x3<M_PV, 32>,    cudaFuncAttributeMaxDynamicSharedMemorySize, SMEM_SZ);

    transpose_w<<<3, 256>>>(Wq, Wk, Wv);

    gemm_bf16x3<M_PROJQK, 8><<<dim3(MTOT / 128, 2, 2), 256, SMEM_SZ>>>(x, bq, bk, bv, out);
    gemm_bf16x3<M_PROJVT, 8><<<dim3(2, 8, BATCH),      256, SMEM_SZ>>>(x, bq, bk, bv, out);
    gemm_bf16x3<M_QK, 8>    <<<dim3(8, 8, BATCH),      256, SMEM_SZ>>>(x, bq, bk, bv, out);
    softmax_rows            <<<MTOT / 8, 256>>>();
    gemm_bf16x3<M_PV, 32>   <<<dim3(8, 2, BATCH),      256, SMEM_SZ>>>(x, bq, bk, bv, out);
}